// round 3
// baseline (speedup 1.0000x reference)
#include <cuda_runtime.h>
#include <cuda_bf16.h>

// YOLOv1 loss: preds [N,7,7,30] f32, labels [N,7,7,30] f32 -> scalar f32.
// HBM-read-bound reduction (192.7 MB in, 4 B out).

#define CELLS_PER_BLOCK 128
#define THREADS 128
#define FLOATS_PER_CELL 30
#define F4_PER_BLOCK (CELLS_PER_BLOCK * FLOATS_PER_CELL / 4)   // 960

__global__ void zero_out_kernel(float* out) { out[0] = 0.0f; }

__device__ __forceinline__ float iou_cxcywh(const float* a, const float* b) {
    float ax1 = a[0] - a[2] * 0.5f, ay1 = a[1] - a[3] * 0.5f;
    float ax2 = a[0] + a[2] * 0.5f, ay2 = a[1] + a[3] * 0.5f;
    float bx1 = b[0] - b[2] * 0.5f, by1 = b[1] - b[3] * 0.5f;
    float bx2 = b[0] + b[2] * 0.5f, by2 = b[1] + b[3] * 0.5f;
    float iw = fmaxf(fminf(ax2, bx2) - fmaxf(ax1, bx1), 0.0f);
    float ih = fmaxf(fminf(ay2, by2) - fmaxf(ay1, by1), 0.0f);
    float inter = iw * ih;
    float uni = a[2] * a[3] + b[2] * b[3] - inter;
    return inter / (uni + 1e-10f);
}

__global__ __launch_bounds__(THREADS) void yolo_loss_kernel(
    const float4* __restrict__ preds4,
    const float4* __restrict__ labels4,
    float* __restrict__ out,
    int n_cells, float inv_batch)
{
    __shared__ float sp[CELLS_PER_BLOCK * FLOATS_PER_CELL];
    __shared__ float sl[CELLS_PER_BLOCK * FLOATS_PER_CELL];
    __shared__ float warp_s[THREADS / 32];

    const int tid = threadIdx.x;
    const long long block_cell0 = (long long)blockIdx.x * CELLS_PER_BLOCK;

    // Number of valid cells in this block (tail-safe; with fixed shapes it's full)
    int valid = n_cells - (int)block_cell0;
    if (valid > CELLS_PER_BLOCK) valid = CELLS_PER_BLOCK;
    const int valid_f4 = (valid * FLOATS_PER_CELL + 3) >> 2;

    // Cooperative, fully coalesced float4 staging of the contiguous block region.
    // Block base in floats = blockIdx * 3840 -> always 16B-aligned.
    const long long base4 = block_cell0 * (FLOATS_PER_CELL / 2) / 2; // = blockIdx*960
    float4* sp4 = reinterpret_cast<float4*>(sp);
    float4* sl4 = reinterpret_cast<float4*>(sl);
#pragma unroll
    for (int i = tid; i < F4_PER_BLOCK; i += THREADS) {
        if (i < valid_f4) {
            sp4[i] = preds4[base4 + i];
            sl4[i] = labels4[base4 + i];
        }
    }
    __syncthreads();

    float loss = 0.0f;
    if (tid < valid) {
        const float* p = &sp[tid * FLOATS_PER_CELL];
        const float* l = &sl[tid * FLOATS_PER_CELL];

        const float obj = (l[4] == 1.0f) ? 1.0f : 0.0f;

        const float i1 = iou_cxcywh(p, l);
        const float i2 = iou_cxcywh(p + 5, l);
        const bool b1 = i1 > i2;

        const float* pr = b1 ? p : (p + 5);      // responsible pred box (+conf at [4])
        const float* po = b1 ? (p + 5) : p;      // other box
        const float* lr = b1 ? l : (l + 5);      // label slice (duplicated in data)
        const float iou_r = b1 ? i1 : i2;
        const float iou_o = b1 ? i2 : i1;

        float dx = pr[0] - lr[0];
        float dy = pr[1] - lr[1];
        float d_xy = dx * dx + dy * dy;

        float sw = sqrtf(pr[2]) - sqrtf(lr[2]);
        float sh = sqrtf(pr[3]) - sqrtf(lr[3]);
        float d_wh = sw * sw + sh * sh;

        float d_obj = pr[4] - iou_r;  d_obj *= d_obj;
        float d_no  = po[4] - iou_o;  d_no  *= d_no;
        float d_out = p[4] * p[4] + p[9] * p[9];

        float d_cls = 0.0f;
#pragma unroll
        for (int c = 10; c < 30; ++c) {
            float d = p[c] - l[c];
            d_cls = fmaf(d, d, d_cls);
        }

        loss = obj * (5.0f * d_xy + d_wh + d_obj + 0.5f * d_no + d_cls)
             + (1.0f - obj) * 0.5f * d_out;
    }

    // Warp reduce
#pragma unroll
    for (int o = 16; o > 0; o >>= 1)
        loss += __shfl_xor_sync(0xffffffffu, loss, o);
    if ((tid & 31) == 0) warp_s[tid >> 5] = loss;
    __syncthreads();

    if (tid == 0) {
        float s = 0.0f;
#pragma unroll
        for (int w = 0; w < THREADS / 32; ++w) s += warp_s[w];
        atomicAdd(out, s * inv_batch);
    }
}

extern "C" void kernel_launch(void* const* d_in, const int* in_sizes, int n_in,
                              void* d_out, int out_size)
{
    const float4* preds4  = (const float4*)d_in[0];
    const float4* labels4 = (const float4*)d_in[1];
    float* out = (float*)d_out;

    const int total_floats = in_sizes[0];                 // N*7*7*30
    const int n_cells = total_floats / FLOATS_PER_CELL;   // N*49
    const int batch = n_cells / 49;                       // N

    zero_out_kernel<<<1, 1>>>(out);

    const int n_blocks = (n_cells + CELLS_PER_BLOCK - 1) / CELLS_PER_BLOCK;
    yolo_loss_kernel<<<n_blocks, THREADS>>>(preds4, labels4, out,
                                            n_cells, 1.0f / (float)batch);
}

// round 6
// speedup vs baseline: 1.1804x; 1.1804x over previous
#include <cuda_runtime.h>
#include <cstdint>

// YOLOv1 loss: preds [N,7,7,30] f32, labels [N,7,7,30] f32 -> scalar f32.
// Persistent double-buffered cp.async pipeline; HBM-bound streaming reduction.

#define TILE_CELLS 96
#define THREADS 96
#define FLOATS_PER_CELL 30
#define F4_PER_ARRAY 720            // 96*30/4
#define F4_PER_TILE 1440            // preds + labels
#define ITERS_PER_STAGE 15          // 1440 / 96 threads
#define MAX_BLOCKS 592              // 4 CTAs/SM * 148 SMs

__global__ void zero_out_kernel(float* out) { out[0] = 0.0f; }

__device__ __forceinline__ uint32_t smem_addr_u32(const void* p) {
    return (uint32_t)__cvta_generic_to_shared(p);
}

#define CP_ASYNC16(dst_u32, src_ptr) \
    asm volatile("cp.async.cg.shared.global [%0], [%1], 16;\n" :: "r"(dst_u32), "l"(src_ptr))
#define CP_COMMIT() asm volatile("cp.async.commit_group;\n" ::)
#define CP_WAIT1()  asm volatile("cp.async.wait_group 1;\n" ::)

__device__ __forceinline__ float iou_cxcywh(const float* a, const float* b) {
    float ax1 = a[0] - a[2] * 0.5f, ay1 = a[1] - a[3] * 0.5f;
    float ax2 = a[0] + a[2] * 0.5f, ay2 = a[1] + a[3] * 0.5f;
    float bx1 = b[0] - b[2] * 0.5f, by1 = b[1] - b[3] * 0.5f;
    float bx2 = b[0] + b[2] * 0.5f, by2 = b[1] + b[3] * 0.5f;
    float iw = fmaxf(fminf(ax2, bx2) - fmaxf(ax1, bx1), 0.0f);
    float ih = fmaxf(fminf(ay2, by2) - fmaxf(ay1, by1), 0.0f);
    float inter = iw * ih;
    float uni = a[2] * a[3] + b[2] * b[3] - inter;
    return inter / (uni + 1e-10f);
}

__global__ __launch_bounds__(THREADS) void yolo_loss_pipe_kernel(
    const float4* __restrict__ preds4,
    const float4* __restrict__ labels4,
    float* __restrict__ out,
    int n_cells, int n_tiles, float inv_batch)
{
    __shared__ float4 buf[2][F4_PER_TILE];   // [stage][preds(720) | labels(720)]
    __shared__ float warp_s[THREADS / 32];

    const int tid = threadIdx.x;

    // Issue one tile's loads into stage s (always commits a group, even if empty).
    auto issue_tile = [&](int t, int s) {
        if (t < n_tiles) {
            const int base = t * F4_PER_ARRAY;
            const int rem = n_cells - t * TILE_CELLS;
            const int vf4 = (rem >= TILE_CELLS) ? F4_PER_ARRAY
                                                : ((rem * FLOATS_PER_CELL + 3) >> 2);
#pragma unroll
            for (int k = 0; k < ITERS_PER_STAGE; ++k) {
                const int i = tid + k * THREADS;           // 0..1439
                const bool is_p = (i < F4_PER_ARRAY);
                const int j = is_p ? i : (i - F4_PER_ARRAY);
                const float4* src = (is_p ? preds4 : labels4) + base + j;
                const uint32_t dst = smem_addr_u32(&buf[s][i]);
                if (j < vf4) CP_ASYNC16(dst, src);
            }
        }
        CP_COMMIT();
    };

    float loss = 0.0f;
    int s = 0;

    // Prologue: prefetch first tile.
    issue_tile((int)blockIdx.x, 0);

    for (int t = blockIdx.x; t < n_tiles; t += gridDim.x) {
        // Keep the next tile's loads in flight while we compute this one.
        issue_tile(t + gridDim.x, s ^ 1);
        CP_WAIT1();                 // stage s complete (stage s^1 may still fly)
        __syncthreads();

        const int cell = t * TILE_CELLS + tid;
        if (cell < n_cells) {
            const float* bp = (const float*)buf[s];
            const float* p = bp + tid * FLOATS_PER_CELL;
            const float* l = bp + 4 * F4_PER_ARRAY + tid * FLOATS_PER_CELL;

            const float obj = (l[4] == 1.0f) ? 1.0f : 0.0f;

            const float i1 = iou_cxcywh(p, l);
            const float i2 = iou_cxcywh(p + 5, l);
            const bool b1 = i1 > i2;

            const float* pr = b1 ? p : (p + 5);
            const float* po = b1 ? (p + 5) : p;
            const float* lr = b1 ? l : (l + 5);   // label box duplicated in data
            const float iou_r = b1 ? i1 : i2;
            const float iou_o = b1 ? i2 : i1;

            float dx = pr[0] - lr[0];
            float dy = pr[1] - lr[1];
            float d_xy = dx * dx + dy * dy;

            float sw = sqrtf(pr[2]) - sqrtf(lr[2]);
            float sh = sqrtf(pr[3]) - sqrtf(lr[3]);
            float d_wh = sw * sw + sh * sh;

            float d_obj = pr[4] - iou_r;  d_obj *= d_obj;
            float d_no  = po[4] - iou_o;  d_no  *= d_no;
            float d_out = p[4] * p[4] + p[9] * p[9];

            float d_cls = 0.0f;
#pragma unroll
            for (int c = 10; c < 30; ++c) {
                float d = p[c] - l[c];
                d_cls = fmaf(d, d, d_cls);
            }

            loss += obj * (5.0f * d_xy + d_wh + d_obj + 0.5f * d_no + d_cls)
                  + (1.0f - obj) * 0.5f * d_out;
        }

        __syncthreads();            // everyone done with stage s before it is refilled
        s ^= 1;
    }

    // Block-level reduction: once per block over the whole persistent run.
#pragma unroll
    for (int o = 16; o > 0; o >>= 1)
        loss += __shfl_xor_sync(0xffffffffu, loss, o);
    if ((tid & 31) == 0) warp_s[tid >> 5] = loss;
    __syncthreads();

    if (tid == 0) {
        float total = 0.0f;
#pragma unroll
        for (int w = 0; w < THREADS / 32; ++w) total += warp_s[w];
        atomicAdd(out, total * inv_batch);
    }
}

extern "C" void kernel_launch(void* const* d_in, const int* in_sizes, int n_in,
                              void* d_out, int out_size)
{
    const float4* preds4  = (const float4*)d_in[0];
    const float4* labels4 = (const float4*)d_in[1];
    float* out = (float*)d_out;

    const int total_floats = in_sizes[0];                    // N*7*7*30
    const int n_cells = total_floats / FLOATS_PER_CELL;      // N*49
    const int batch = n_cells / 49;                          // N
    const int n_tiles = (n_cells + TILE_CELLS - 1) / TILE_CELLS;

    zero_out_kernel<<<1, 1>>>(out);

    const int n_blocks = (n_tiles < MAX_BLOCKS) ? n_tiles : MAX_BLOCKS;
    yolo_loss_pipe_kernel<<<n_blocks, THREADS>>>(preds4, labels4, out,
                                                 n_cells, n_tiles,
                                                 1.0f / (float)batch);
}